// round 3
// baseline (speedup 1.0000x reference)
#include <cuda_runtime.h>
#include <math.h>

// Problem constants
#define NN   102400      // nodes
#define EE   1228800     // edges
#define NB   2048        // graphs
#define TT   50          // nodes per graph
#define EPG  600         // edges per graph
#define KIN  576         // IN + POS
#define HH   512         // hidden / out
#define POSD 64

#define CH   64          // channels per aggregation block (static smem fits)

// ---------------- scratch (static device globals; no runtime allocation) ----
__device__ float g_xc[(size_t)NN * KIN];
__device__ float g_t [(size_t)NN * HH];
__device__ float g_p1[(size_t)NN * HH];
__device__ float g_p2[(size_t)NN * HH];
__device__ float g_p3[(size_t)NN * HH];
__device__ float g_norm[EE];
__device__ float g_dinv[NN];
__device__ float g_deg [NN];
__device__ float g_stats[2 * HH];     // [sum | sumsq], re-zeroed in bnfinal
__device__ float g_scale[3 * HH];     // folded BN scale per layer
__device__ float g_shift[3 * HH];     // folded BN shift per layer

// ---------------- concat x || posemb[pos] --------------------------------
__global__ void concat_k(const float* __restrict__ x, const int* __restrict__ pos,
                         const float* __restrict__ posemb)
{
    int node = blockIdx.x;
    int j = threadIdx.x;
    float v;
    if (j < HH) v = x[(size_t)node * HH + j];
    else        v = posemb[pos[node] * POSD + (j - HH)];
    g_xc[(size_t)node * KIN + j] = v;
}

// ---------------- degree / normalization ---------------------------------
__global__ void deg_init_k()
{
    int i = blockIdx.x * blockDim.x + threadIdx.x;
    if (i < NN) g_deg[i] = 1.0f;   // self-loop weight
}

__global__ void deg_acc_k(const int* __restrict__ dst, const float* __restrict__ w)
{
    int e = blockIdx.x * blockDim.x + threadIdx.x;
    if (e < EE) atomicAdd(&g_deg[dst[e]], w[e]);
}

__global__ void dinv_k()
{
    int i = blockIdx.x * blockDim.x + threadIdx.x;
    if (i < NN) g_dinv[i] = rsqrtf(g_deg[i]);
}

__global__ void norm_k(const int* __restrict__ src, const int* __restrict__ dst,
                       const float* __restrict__ w)
{
    int e = blockIdx.x * blockDim.x + threadIdx.x;
    if (e < EE) g_norm[e] = g_dinv[src[e]] * w[e] * g_dinv[dst[e]];
}

// ---------------- tiled fp32 GEMM with fused BN+ReLU on A-load ------------
// SRC: 0=g_xc 1=g_p1 2=g_p2 3=g_t ; ACTL: -1 none, else layer index for scale/shift
// MODE 0: C = g_t ; MODE 1: out = tanh(acc + bias)
template<int MODE, int SRC, int ACTL, int KDIM>
__global__ void __launch_bounds__(256, 2) sgemm_k(
    const float* __restrict__ B, float* __restrict__ outC,
    const float* __restrict__ bias)
{
    const float* A = (SRC == 0) ? g_xc : (SRC == 1) ? g_p1 : (SRC == 2) ? g_p2 : g_t;
    float* C = (MODE == 0) ? g_t : outC;
    const float* aScale = (ACTL >= 0) ? (g_scale + ACTL * HH) : nullptr;
    const float* aShift = (ACTL >= 0) ? (g_shift + ACTL * HH) : nullptr;

    __shared__ float As[8 * 128];   // transposed: As[k][m]
    __shared__ float Bs[8 * 128];   // Bs[k][n]
    const int tid  = threadIdx.x;
    const int tRow = tid / 16, tCol = tid % 16;
    const int iRowA = tid / 2,  iColA = (tid & 1) * 4;
    const int iRowB = tid / 32, iColB = (tid & 31) * 4;

    const float* Ab = A + (size_t)blockIdx.y * 128 * KDIM;
    const float* Bb = B + blockIdx.x * 128;

    float acc[8][8] = {};

    #pragma unroll 1
    for (int k0 = 0; k0 < KDIM; k0 += 8) {
        float4 a = *(const float4*)(Ab + (size_t)iRowA * KDIM + k0 + iColA);
        if (ACTL >= 0) {
            float4 s = *(const float4*)(aScale + k0 + iColA);
            float4 h = *(const float4*)(aShift + k0 + iColA);
            a.x = fmaxf(fmaf(a.x, s.x, h.x), 0.f);
            a.y = fmaxf(fmaf(a.y, s.y, h.y), 0.f);
            a.z = fmaxf(fmaf(a.z, s.z, h.z), 0.f);
            a.w = fmaxf(fmaf(a.w, s.w, h.w), 0.f);
        }
        As[(iColA + 0) * 128 + iRowA] = a.x;
        As[(iColA + 1) * 128 + iRowA] = a.y;
        As[(iColA + 2) * 128 + iRowA] = a.z;
        As[(iColA + 3) * 128 + iRowA] = a.w;
        *(float4*)&Bs[iRowB * 128 + iColB] =
            *(const float4*)(Bb + (size_t)(k0 + iRowB) * HH + iColB);
        __syncthreads();

        #pragma unroll
        for (int kk = 0; kk < 8; ++kk) {
            float rM[8], rN[8];
            #pragma unroll
            for (int i = 0; i < 8; ++i) rM[i] = As[kk * 128 + tRow * 8 + i];
            #pragma unroll
            for (int j = 0; j < 8; ++j) rN[j] = Bs[kk * 128 + tCol * 8 + j];
            #pragma unroll
            for (int i = 0; i < 8; ++i)
                #pragma unroll
                for (int j = 0; j < 8; ++j)
                    acc[i][j] = fmaf(rM[i], rN[j], acc[i][j]);
        }
        __syncthreads();
    }

    const size_t rowBase = (size_t)blockIdx.y * 128 + tRow * 8;
    const int    colBase = blockIdx.x * 128 + tCol * 8;
    #pragma unroll
    for (int i = 0; i < 8; ++i) {
        #pragma unroll
        for (int j4 = 0; j4 < 8; j4 += 4) {
            float4 o;
            float* v = &o.x;
            #pragma unroll
            for (int j = 0; j < 4; ++j) {
                float val = acc[i][j4 + j];
                if (MODE == 1) val = tanhf(val + bias[colBase + j4 + j]);
                v[j] = val;
            }
            *(float4*)(C + (rowBase + i) * HH + colBase + j4) = o;
        }
    }
}

// ---------------- per-graph aggregation in SMEM + bias + BN partial stats --
// block = (graph b, channel chunk); 64 threads, each owns one channel column.
// L selects output buffer: 0->g_p1, 1->g_p2, 2->g_p3. Input is g_t.
template<int L>
__global__ void __launch_bounds__(64) agg_k(
    const int* __restrict__ src, const int* __restrict__ dst,
    const float* __restrict__ bias)
{
    __shared__ float sIn [TT * CH];
    __shared__ float sAcc[TT * CH];
    __shared__ float sNorm[EPG];
    __shared__ float sSelf[TT];
    __shared__ int   sSrc[EPG];
    __shared__ int   sDst[EPG];

    float* pout = (L == 0) ? g_p1 : (L == 1) ? g_p2 : g_p3;

    const int b   = blockIdx.x;
    const int c0  = blockIdx.y * CH;
    const int tid = threadIdx.x;

    const float* base = g_t + (size_t)b * TT * HH + c0;
    for (int i = tid; i < TT * CH; i += 64) {
        int node = i / CH, c = i & (CH - 1);
        sIn[i]  = base[(size_t)node * HH + c];
        sAcc[i] = 0.f;
    }
    for (int e = tid; e < EPG; e += 64) {
        sSrc[e]  = src[b * EPG + e] - b * TT;
        sDst[e]  = dst[b * EPG + e] - b * TT;
        sNorm[e] = g_norm[b * EPG + e];
    }
    for (int i = tid; i < TT; i += 64) {
        float d = g_dinv[b * TT + i];
        sSelf[i] = d * d;   // self-loop norm
    }
    __syncthreads();

    const int c = tid;
    #pragma unroll 4
    for (int e = 0; e < EPG; ++e) {
        sAcc[sDst[e] * CH + c] += sIn[sSrc[e] * CH + c] * sNorm[e];
    }
    // no sync needed: each thread touches only its own channel column

    const float bc = bias[c0 + c];
    float sum = 0.f, sq = 0.f;
    for (int node = 0; node < TT; ++node) {
        float v = sAcc[node * CH + c] + sIn[node * CH + c] * sSelf[node] + bc;
        pout[(size_t)(b * TT + node) * HH + c0 + c] = v;
        sum += v;
        sq  += v * v;
    }
    atomicAdd(&g_stats[c0 + c], sum);
    atomicAdd(&g_stats[HH + c0 + c], sq);
}

// ---------------- BN finalize: fold gamma/beta into scale/shift -----------
template<int L>
__global__ void bnfinal_k(const float* __restrict__ g, const float* __restrict__ be)
{
    int c = threadIdx.x;
    float s = g_stats[c], sq = g_stats[HH + c];
    const float inv = 1.0f / (float)NN;
    float mean = s * inv;
    float var  = sq * inv - mean * mean;
    float rstd = rsqrtf(var + 1e-5f);
    float scl  = g[c] * rstd;
    g_scale[L * HH + c] = scl;
    g_shift[L * HH + c] = fmaf(-mean, scl, be[c]);
    g_stats[c] = 0.f;             // re-zero for next replay (determinism)
    g_stats[HH + c] = 0.f;
}

// ---------------- residual combine into g_t -------------------------------
__global__ void combine_k()
{
    size_t idx = (size_t)blockIdx.x * blockDim.x + threadIdx.x;
    int c4 = (int)(idx & (HH / 4 - 1));
    const float4* p1 = (const float4*)g_p1;
    const float4* p2 = (const float4*)g_p2;
    const float4* p3 = (const float4*)g_p3;
    const float4* sc = (const float4*)g_scale;
    const float4* sh = (const float4*)g_shift;
    float4 a = p1[idx], b = p2[idx], c = p3[idx];
    float4 s, h, r;
    s = sc[c4];       h = sh[c4];
    r.x = fmaxf(fmaf(a.x, s.x, h.x), 0.f);
    r.y = fmaxf(fmaf(a.y, s.y, h.y), 0.f);
    r.z = fmaxf(fmaf(a.z, s.z, h.z), 0.f);
    r.w = fmaxf(fmaf(a.w, s.w, h.w), 0.f);
    s = sc[128 + c4]; h = sh[128 + c4];
    r.x += fmaxf(fmaf(b.x, s.x, h.x), 0.f);
    r.y += fmaxf(fmaf(b.y, s.y, h.y), 0.f);
    r.z += fmaxf(fmaf(b.z, s.z, h.z), 0.f);
    r.w += fmaxf(fmaf(b.w, s.w, h.w), 0.f);
    s = sc[256 + c4]; h = sh[256 + c4];
    r.x += fmaxf(fmaf(c.x, s.x, h.x), 0.f);
    r.y += fmaxf(fmaf(c.y, s.y, h.y), 0.f);
    r.z += fmaxf(fmaf(c.z, s.z, h.z), 0.f);
    r.w += fmaxf(fmaf(c.w, s.w, h.w), 0.f);
    ((float4*)g_t)[idx] = r;
}

// ---------------- host driver: kernel launches ONLY ------------------------
extern "C" void kernel_launch(void* const* d_in, const int* in_sizes, int n_in,
                              void* d_out, int out_size)
{
    (void)in_sizes; (void)n_in; (void)out_size;

    const float* x      = (const float*)d_in[0];
    const int*   eidx   = (const int*)  d_in[1];
    const int*   esrc   = eidx;
    const int*   edst   = eidx + EE;
    const float* ew     = (const float*)d_in[2];
    const int*   pos    = (const int*)  d_in[3];
    const float* posemb = (const float*)d_in[4];
    const float* W1 = (const float*)d_in[5];
    const float* b1 = (const float*)d_in[6];
    const float* g1 = (const float*)d_in[7];
    const float* be1= (const float*)d_in[8];
    const float* W2 = (const float*)d_in[9];
    const float* b2 = (const float*)d_in[10];
    const float* g2 = (const float*)d_in[11];
    const float* be2= (const float*)d_in[12];
    const float* W3 = (const float*)d_in[13];
    const float* b3 = (const float*)d_in[14];
    const float* g3 = (const float*)d_in[15];
    const float* be3= (const float*)d_in[16];
    const float* Wl = (const float*)d_in[17];
    const float* bl = (const float*)d_in[18];
    float* out = (float*)d_out;

    dim3 gGrid(HH / 128, NN / 128);   // (4, 800)
    dim3 aGrid(NB, HH / CH);          // (2048, 8)

    // 0) concat + normalization precompute
    concat_k<<<NN, KIN>>>(x, pos, posemb);
    deg_init_k<<<(NN + 255) / 256, 256>>>();
    deg_acc_k<<<(EE + 255) / 256, 256>>>(edst, ew);
    dinv_k<<<(NN + 255) / 256, 256>>>();
    norm_k<<<(EE + 255) / 256, 256>>>(esrc, edst, ew);

    // layer 1: g_t = g_xc @ W1 ; g_p1 = agg(g_t) + b1 ; fold BN1
    sgemm_k<0, 0, -1, KIN><<<gGrid, 256>>>(W1, nullptr, nullptr);
    agg_k<0><<<aGrid, 64>>>(esrc, edst, b1);
    bnfinal_k<0><<<1, HH>>>(g1, be1);

    // layer 2: g_t = relu(bn1(g_p1)) @ W2 ; g_p2 = agg(g_t) + b2 ; fold BN2
    sgemm_k<0, 1, 0, HH><<<gGrid, 256>>>(W2, nullptr, nullptr);
    agg_k<1><<<aGrid, 64>>>(esrc, edst, b2);
    bnfinal_k<1><<<1, HH>>>(g2, be2);

    // layer 3: g_t = relu(bn2(g_p2)) @ W3 ; g_p3 = agg(g_t) + b3 ; fold BN3
    sgemm_k<0, 2, 1, HH><<<gGrid, 256>>>(W3, nullptr, nullptr);
    agg_k<2><<<aGrid, 64>>>(esrc, edst, b3);
    bnfinal_k<2><<<1, HH>>>(g3, be3);

    // residual combine into g_t, then out = tanh(g_t @ Wl + bl)
    combine_k<<<(NN * HH / 4) / 256, 256>>>();
    sgemm_k<1, 3, -1, HH><<<gGrid, 256>>>(Wl, out, bl);
}

// round 6
// speedup vs baseline: 1.2413x; 1.2413x over previous
#include <cuda_runtime.h>
#include <cuda_bf16.h>
#include <math.h>
#include <stdint.h>

// Problem constants
#define NN   102400      // nodes
#define EE   1228800     // edges
#define NB   2048        // graphs
#define TT   50          // nodes per graph
#define EPG  600         // edges per graph
#define KIN  576         // IN + POS
#define HH   512         // hidden / out
#define POSD 64

#define CH   64          // channels per aggregation block (static smem fits)
#define SAPAD 40         // smem row stride in bf16 (conflict-free frag loads)

// ---------------- scratch (static device globals; no runtime allocation) ----
__device__ float g_xc[(size_t)NN * KIN];
__device__ float g_t [(size_t)NN * HH];
__device__ float g_p1[(size_t)NN * HH];
__device__ float g_p2[(size_t)NN * HH];
__device__ float g_p3[(size_t)NN * HH];
__device__ float g_norm[EE];
__device__ float g_dinv[NN];
__device__ float g_deg [NN];
__device__ float g_stats[2 * HH];
__device__ float g_scale[3 * HH];
__device__ float g_shift[3 * HH];

// ---------------- concat x || posemb[pos] ---------------------------------
__global__ void concat_k(const float* __restrict__ x, const int* __restrict__ pos,
                         const float* __restrict__ posemb)
{
    int node = blockIdx.x;
    int j = threadIdx.x;
    float v;
    if (j < HH) v = x[(size_t)node * HH + j];
    else        v = posemb[pos[node] * POSD + (j - HH)];
    g_xc[(size_t)node * KIN + j] = v;
}

// ---------------- degree / normalization ----------------------------------
__global__ void deg_init_k()
{
    int i = blockIdx.x * blockDim.x + threadIdx.x;
    if (i < NN) g_deg[i] = 1.0f;
}
__global__ void deg_acc_k(const int* __restrict__ dst, const float* __restrict__ w)
{
    int e = blockIdx.x * blockDim.x + threadIdx.x;
    if (e < EE) atomicAdd(&g_deg[dst[e]], w[e]);
}
__global__ void dinv_k()
{
    int i = blockIdx.x * blockDim.x + threadIdx.x;
    if (i < NN) g_dinv[i] = rsqrtf(g_deg[i]);
}
__global__ void norm_k(const int* __restrict__ src, const int* __restrict__ dst,
                       const float* __restrict__ w)
{
    int e = blockIdx.x * blockDim.x + threadIdx.x;
    if (e < EE) g_norm[e] = g_dinv[src[e]] * w[e] * g_dinv[dst[e]];
}

// ---------------- HMMA helper ----------------------------------------------
__device__ __forceinline__ void mma_bf16(float* c, const uint32_t* a,
                                         uint32_t b0, uint32_t b1)
{
    asm volatile(
        "mma.sync.aligned.m16n8k16.row.col.f32.bf16.bf16.f32 "
        "{%0,%1,%2,%3}, {%4,%5,%6,%7}, {%8,%9}, {%0,%1,%2,%3};"
        : "+f"(c[0]), "+f"(c[1]), "+f"(c[2]), "+f"(c[3])
        : "r"(a[0]), "r"(a[1]), "r"(a[2]), "r"(a[3]), "r"(b0), "r"(b1));
}

__device__ __forceinline__ uint32_t pack_bf16x2(float x, float y)
{
    __nv_bfloat162 h = __floats2bfloat162_rn(x, y);
    return *(uint32_t*)&h;
}

// ---------------- split-bf16 HMMA GEMM -------------------------------------
// C[M=128, N=128 per CTA] = act(A)[.,K] @ W[K,HH] (N-slice)
// 3 split MMAs: hi*hi + hi*lo + lo*hi, fp32 accum.
// MODE 0: C -> g_t ; MODE 1: out = tanh(acc + bias)
// SRC: 0=g_xc 1=g_p1 2=g_p2 3=g_t ; ACTL: BN layer index or -1
template<int MODE, int SRC, int ACTL, int KDIM>
__global__ void __launch_bounds__(256) gemm_hmma(
    const float* __restrict__ W, float* __restrict__ outC,
    const float* __restrict__ bias)
{
    __shared__ uint16_t sAhi[128 * SAPAD];
    __shared__ uint16_t sAlo[128 * SAPAD];
    __shared__ uint16_t sBhi[128 * SAPAD];
    __shared__ uint16_t sBlo[128 * SAPAD];

    const int tid  = threadIdx.x;
    const int wid  = tid >> 5;
    const int lane = tid & 31;
    const int g    = lane >> 2;        // groupID 0..7
    const int tig  = lane & 3;         // thread-in-group 0..3
    const int wm   = wid & 3;          // warp m-tile 0..3 (32 rows each)
    const int wn   = wid >> 2;         // warp n-tile 0..1 (64 cols each)

    const float* A = (SRC == 0) ? g_xc : (SRC == 1) ? g_p1 : (SRC == 2) ? g_p2 : g_t;
    const int n0      = blockIdx.x * 128;
    const size_t rowBase = (size_t)blockIdx.y * 128;

    float acc[2][8][4];
    #pragma unroll
    for (int fm = 0; fm < 2; ++fm)
        #pragma unroll
        for (int fn = 0; fn < 8; ++fn)
            #pragma unroll
            for (int q = 0; q < 4; ++q) acc[fm][fn][q] = 0.f;

    for (int k0 = 0; k0 < KDIM; k0 += 32) {
        // ---- load A tile (128 x 32 fp32), fuse BN+ReLU, split hi/lo --------
        #pragma unroll
        for (int i = 0; i < 4; ++i) {
            int idx = i * 256 + tid;            // 0..1023 float4s
            int row = idx >> 3, c4 = idx & 7;   // k = c4*4
            const float* ap = A + (rowBase + row) * KDIM + k0 + c4 * 4;
            float4 v = *(const float4*)ap;
            if (ACTL >= 0) {
                int k = k0 + c4 * 4;
                float4 s = *(const float4*)(g_scale + ACTL * HH + k);
                float4 h = *(const float4*)(g_shift + ACTL * HH + k);
                v.x = fmaxf(fmaf(v.x, s.x, h.x), 0.f);
                v.y = fmaxf(fmaf(v.y, s.y, h.y), 0.f);
                v.z = fmaxf(fmaf(v.z, s.z, h.z), 0.f);
                v.w = fmaxf(fmaf(v.w, s.w, h.w), 0.f);
            }
            __nv_bfloat16 h0 = __float2bfloat16(v.x), h1 = __float2bfloat16(v.y);
            __nv_bfloat16 h2 = __float2bfloat16(v.z), h3 = __float2bfloat16(v.w);
            float r0 = v.x - __bfloat162float(h0), r1 = v.y - __bfloat162float(h1);
            float r2 = v.z - __bfloat162float(h2), r3 = v.w - __bfloat162float(h3);
            uint32_t* dhi = (uint32_t*)&sAhi[row * SAPAD + c4 * 4];
            uint32_t* dlo = (uint32_t*)&sAlo[row * SAPAD + c4 * 4];
            dhi[0] = ((uint32_t)__bfloat16_as_ushort(h1) << 16) | __bfloat16_as_ushort(h0);
            dhi[1] = ((uint32_t)__bfloat16_as_ushort(h3) << 16) | __bfloat16_as_ushort(h2);
            dlo[0] = pack_bf16x2(r0, r1);
            dlo[1] = pack_bf16x2(r2, r3);
        }
        // ---- load W tile (32 x 128 fp32), transpose to [n][k], split -------
        #pragma unroll
        for (int i = 0; i < 16; ++i) {
            int idx = i * 256 + tid;            // 0..4095
            int k = idx >> 7, n = idx & 127;
            float v = W[(size_t)(k0 + k) * HH + n0 + n];
            __nv_bfloat16 h = __float2bfloat16(v);
            float r = v - __bfloat162float(h);
            sBhi[n * SAPAD + k] = __bfloat16_as_ushort(h);
            sBlo[n * SAPAD + k] = __bfloat16_as_ushort(__float2bfloat16(r));
        }
        __syncthreads();

        // ---- MMA over this chunk ------------------------------------------
        #pragma unroll
        for (int ks = 0; ks < 2; ++ks) {
            const int kc = ks * 16 + 2 * tig;
            uint32_t af[2][2][4];   // [hi/lo][fm][reg]
            #pragma unroll
            for (int fm = 0; fm < 2; ++fm) {
                int r0 = (wm * 32 + fm * 16 + g) * SAPAD;
                int r1 = r0 + 8 * SAPAD;
                af[0][fm][0] = *(uint32_t*)&sAhi[r0 + kc];
                af[0][fm][1] = *(uint32_t*)&sAhi[r1 + kc];
                af[0][fm][2] = *(uint32_t*)&sAhi[r0 + kc + 8];
                af[0][fm][3] = *(uint32_t*)&sAhi[r1 + kc + 8];
                af[1][fm][0] = *(uint32_t*)&sAlo[r0 + kc];
                af[1][fm][1] = *(uint32_t*)&sAlo[r1 + kc];
                af[1][fm][2] = *(uint32_t*)&sAlo[r0 + kc + 8];
                af[1][fm][3] = *(uint32_t*)&sAlo[r1 + kc + 8];
            }
            #pragma unroll
            for (int fn = 0; fn < 8; ++fn) {
                int bn = (wn * 64 + fn * 8 + g) * SAPAD;
                uint32_t bh0 = *(uint32_t*)&sBhi[bn + kc];
                uint32_t bh1 = *(uint32_t*)&sBhi[bn + kc + 8];
                uint32_t bl0 = *(uint32_t*)&sBlo[bn + kc];
                uint32_t bl1 = *(uint32_t*)&sBlo[bn + kc + 8];
                #pragma unroll
                for (int fm = 0; fm < 2; ++fm) {
                    mma_bf16(acc[fm][fn], af[0][fm], bh0, bh1);   // hi*hi
                    mma_bf16(acc[fm][fn], af[0][fm], bl0, bl1);   // hi*lo
                    mma_bf16(acc[fm][fn], af[1][fm], bh0, bh1);   // lo*hi
                }
            }
        }
        __syncthreads();
    }

    // ---- epilogue --------------------------------------------------------
    float* Cout = (MODE == 0) ? g_t : outC;
    #pragma unroll
    for (int fm = 0; fm < 2; ++fm) {
        size_t r0 = rowBase + wm * 32 + fm * 16 + g;
        size_t r1 = r0 + 8;
        #pragma unroll
        for (int fn = 0; fn < 8; ++fn) {
            int col = n0 + wn * 64 + fn * 8 + 2 * tig;
            float2 v0, v1;
            if (MODE == 0) {
                v0.x = acc[fm][fn][0]; v0.y = acc[fm][fn][1];
                v1.x = acc[fm][fn][2]; v1.y = acc[fm][fn][3];
            } else {
                float bx = bias[col], by = bias[col + 1];
                v0.x = tanhf(acc[fm][fn][0] + bx);
                v0.y = tanhf(acc[fm][fn][1] + by);
                v1.x = tanhf(acc[fm][fn][2] + bx);
                v1.y = tanhf(acc[fm][fn][3] + by);
            }
            *(float2*)(Cout + r0 * HH + col) = v0;
            *(float2*)(Cout + r1 * HH + col) = v1;
        }
    }
}

// ---------------- per-graph aggregation (unchanged from passing R3) --------
template<int L>
__global__ void __launch_bounds__(64) agg_k(
    const int* __restrict__ src, const int* __restrict__ dst,
    const float* __restrict__ bias)
{
    __shared__ float sIn [TT * CH];
    __shared__ float sAcc[TT * CH];
    __shared__ float sNorm[EPG];
    __shared__ float sSelf[TT];
    __shared__ int   sSrc[EPG];
    __shared__ int   sDst[EPG];

    float* pout = (L == 0) ? g_p1 : (L == 1) ? g_p2 : g_p3;

    const int b   = blockIdx.x;
    const int c0  = blockIdx.y * CH;
    const int tid = threadIdx.x;

    const float* base = g_t + (size_t)b * TT * HH + c0;
    for (int i = tid; i < TT * CH; i += 64) {
        int node = i / CH, c = i & (CH - 1);
        sIn[i]  = base[(size_t)node * HH + c];
        sAcc[i] = 0.f;
    }
    for (int e = tid; e < EPG; e += 64) {
        sSrc[e]  = src[b * EPG + e] - b * TT;
        sDst[e]  = dst[b * EPG + e] - b * TT;
        sNorm[e] = g_norm[b * EPG + e];
    }
    for (int i = tid; i < TT; i += 64) {
        float d = g_dinv[b * TT + i];
        sSelf[i] = d * d;
    }
    __syncthreads();

    const int c = tid;
    #pragma unroll 4
    for (int e = 0; e < EPG; ++e) {
        sAcc[sDst[e] * CH + c] += sIn[sSrc[e] * CH + c] * sNorm[e];
    }

    const float bc = bias[c0 + c];
    float sum = 0.f, sq = 0.f;
    for (int node = 0; node < TT; ++node) {
        float v = sAcc[node * CH + c] + sIn[node * CH + c] * sSelf[node] + bc;
        pout[(size_t)(b * TT + node) * HH + c0 + c] = v;
        sum += v;
        sq  += v * v;
    }
    atomicAdd(&g_stats[c0 + c], sum);
    atomicAdd(&g_stats[HH + c0 + c], sq);
}

// ---------------- BN finalize ----------------------------------------------
template<int L>
__global__ void bnfinal_k(const float* __restrict__ g, const float* __restrict__ be)
{
    int c = threadIdx.x;
    float s = g_stats[c], sq = g_stats[HH + c];
    const float inv = 1.0f / (float)NN;
    float mean = s * inv;
    float var  = sq * inv - mean * mean;
    float rstd = rsqrtf(var + 1e-5f);
    float scl  = g[c] * rstd;
    g_scale[L * HH + c] = scl;
    g_shift[L * HH + c] = fmaf(-mean, scl, be[c]);
    g_stats[c] = 0.f;
    g_stats[HH + c] = 0.f;
}

// ---------------- residual combine into g_t --------------------------------
__global__ void combine_k()
{
    size_t idx = (size_t)blockIdx.x * blockDim.x + threadIdx.x;
    int c4 = (int)(idx & (HH / 4 - 1));
    const float4* p1 = (const float4*)g_p1;
    const float4* p2 = (const float4*)g_p2;
    const float4* p3 = (const float4*)g_p3;
    const float4* sc = (const float4*)g_scale;
    const float4* sh = (const float4*)g_shift;
    float4 a = p1[idx], b = p2[idx], c = p3[idx];
    float4 s, h, r;
    s = sc[c4];       h = sh[c4];
    r.x = fmaxf(fmaf(a.x, s.x, h.x), 0.f);
    r.y = fmaxf(fmaf(a.y, s.y, h.y), 0.f);
    r.z = fmaxf(fmaf(a.z, s.z, h.z), 0.f);
    r.w = fmaxf(fmaf(a.w, s.w, h.w), 0.f);
    s = sc[128 + c4]; h = sh[128 + c4];
    r.x += fmaxf(fmaf(b.x, s.x, h.x), 0.f);
    r.y += fmaxf(fmaf(b.y, s.y, h.y), 0.f);
    r.z += fmaxf(fmaf(b.z, s.z, h.z), 0.f);
    r.w += fmaxf(fmaf(b.w, s.w, h.w), 0.f);
    s = sc[256 + c4]; h = sh[256 + c4];
    r.x += fmaxf(fmaf(c.x, s.x, h.x), 0.f);
    r.y += fmaxf(fmaf(c.y, s.y, h.y), 0.f);
    r.z += fmaxf(fmaf(c.z, s.z, h.z), 0.f);
    r.w += fmaxf(fmaf(c.w, s.w, h.w), 0.f);
    ((float4*)g_t)[idx] = r;
}

// ---------------- host driver ----------------------------------------------
extern "C" void kernel_launch(void* const* d_in, const int* in_sizes, int n_in,
                              void* d_out, int out_size)
{
    (void)in_sizes; (void)n_in; (void)out_size;

    const float* x      = (const float*)d_in[0];
    const int*   eidx   = (const int*)  d_in[1];
    const int*   esrc   = eidx;
    const int*   edst   = eidx + EE;
    const float* ew     = (const float*)d_in[2];
    const int*   pos    = (const int*)  d_in[3];
    const float* posemb = (const float*)d_in[4];
    const float* W1 = (const float*)d_in[5];
    const float* b1 = (const float*)d_in[6];
    const float* g1 = (const float*)d_in[7];
    const float* be1= (const float*)d_in[8];
    const float* W2 = (const float*)d_in[9];
    const float* b2 = (const float*)d_in[10];
    const float* g2 = (const float*)d_in[11];
    const float* be2= (const float*)d_in[12];
    const float* W3 = (const float*)d_in[13];
    const float* b3 = (const float*)d_in[14];
    const float* g3 = (const float*)d_in[15];
    const float* be3= (const float*)d_in[16];
    const float* Wl = (const float*)d_in[17];
    const float* bl = (const float*)d_in[18];
    float* out = (float*)d_out;

    dim3 aGrid(NB, HH / CH);          // (2048, 8)
    dim3 gGrid(HH / 128, NN / 128);   // (4, 800)

    // 0) concat + normalization precompute
    concat_k<<<NN, KIN>>>(x, pos, posemb);
    deg_init_k<<<(NN + 255) / 256, 256>>>();
    deg_acc_k<<<(EE + 255) / 256, 256>>>(edst, ew);
    dinv_k<<<(NN + 255) / 256, 256>>>();
    norm_k<<<(EE + 255) / 256, 256>>>(esrc, edst, ew);

    // layer 1: g_t = g_xc @ W1 ; g_p1 = agg(g_t) + b1 ; fold BN1
    gemm_hmma<0, 0, -1, KIN><<<gGrid, 256>>>(W1, nullptr, nullptr);
    agg_k<0><<<aGrid, 64>>>(esrc, edst, b1);
    bnfinal_k<0><<<1, HH>>>(g1, be1);

    // layer 2: g_t = relu(bn1(g_p1)) @ W2 ; g_p2 = agg(g_t) + b2 ; fold BN2
    gemm_hmma<0, 1, 0, HH><<<gGrid, 256>>>(W2, nullptr, nullptr);
    agg_k<1><<<aGrid, 64>>>(esrc, edst, b2);
    bnfinal_k<1><<<1, HH>>>(g2, be2);

    // layer 3: g_t = relu(bn2(g_p2)) @ W3 ; g_p3 = agg(g_t) + b3 ; fold BN3
    gemm_hmma<0, 2, 1, HH><<<gGrid, 256>>>(W3, nullptr, nullptr);
    agg_k<2><<<aGrid, 64>>>(esrc, edst, b3);
    bnfinal_k<2><<<1, HH>>>(g3, be3);

    // residual combine + final head
    combine_k<<<(NN * HH / 4) / 256, 256>>>();
    gemm_hmma<1, 3, -1, HH><<<gGrid, 256>>>(Wl, out, bl);
}

// round 7
// speedup vs baseline: 1.5767x; 1.2702x over previous
#include <cuda_runtime.h>
#include <cuda_bf16.h>
#include <math.h>
#include <stdint.h>

// Problem constants
#define NN   102400      // nodes
#define EE   1228800     // edges
#define NB   2048        // graphs
#define TT   50          // nodes per graph
#define EPG  600         // edges per graph
#define KIN  576         // IN + POS
#define HH   512         // hidden / out
#define POSD 64

#define CH   64          // channels per aggregation block
#define SAPAD 40         // smem row stride in bf16 (conflict-free frag loads)
#define WSTR 576         // global stride of pre-split weight rows [n][k]

// ---------------- scratch (static device globals) ---------------------------
__device__ uint16_t g_ahi[(size_t)NN * KIN];   // activation hi (bf16 bits)
__device__ uint16_t g_alo[(size_t)NN * KIN];   // activation lo
__device__ uint16_t g_whi[4][(size_t)HH * WSTR];  // weights [n][k] hi
__device__ uint16_t g_wlo[4][(size_t)HH * WSTR];  // weights [n][k] lo
__device__ float g_t [(size_t)NN * HH];
__device__ float g_p1[(size_t)NN * HH];
__device__ float g_p2[(size_t)NN * HH];
__device__ float g_p3[(size_t)NN * HH];
__device__ float g_norm[EE];
__device__ float g_dinv[NN];
__device__ float g_deg [NN];
__device__ float g_stats[2 * HH];
__device__ float g_scale[3 * HH];
__device__ float g_shift[3 * HH];

// ---------------- helpers ---------------------------------------------------
__device__ __forceinline__ void split_bf16(float v, uint16_t& h, uint16_t& l)
{
    __nv_bfloat16 hb = __float2bfloat16(v);
    h = __bfloat16_as_ushort(hb);
    l = __bfloat16_as_ushort(__float2bfloat16(v - __bfloat162float(hb)));
}
__device__ __forceinline__ void mma_bf16(float* c, const uint32_t* a,
                                         uint32_t b0, uint32_t b1)
{
    asm volatile(
        "mma.sync.aligned.m16n8k16.row.col.f32.bf16.bf16.f32 "
        "{%0,%1,%2,%3}, {%4,%5,%6,%7}, {%8,%9}, {%0,%1,%2,%3};"
        : "+f"(c[0]), "+f"(c[1]), "+f"(c[2]), "+f"(c[3])
        : "r"(a[0]), "r"(a[1]), "r"(a[2]), "r"(a[3]), "r"(b0), "r"(b1));
}

// ---------------- concat x || posemb[pos] -> split bf16 ---------------------
__global__ void concat_split_k(const float* __restrict__ x, const int* __restrict__ pos,
                               const float* __restrict__ posemb)
{
    int node = blockIdx.x;
    int j = threadIdx.x;
    float v;
    if (j < HH) v = x[(size_t)node * HH + j];
    else        v = posemb[pos[node] * POSD + (j - HH)];
    uint16_t h, l;
    split_bf16(v, h, l);
    g_ahi[(size_t)node * KIN + j] = h;
    g_alo[(size_t)node * KIN + j] = l;
}

// ---------------- degree / normalization ------------------------------------
__global__ void deg_init_k()
{
    int i = blockIdx.x * blockDim.x + threadIdx.x;
    if (i < NN) g_deg[i] = 1.0f;
}
__global__ void deg_acc_k(const int* __restrict__ dst, const float* __restrict__ w)
{
    int e = blockIdx.x * blockDim.x + threadIdx.x;
    if (e < EE) atomicAdd(&g_deg[dst[e]], w[e]);
}
__global__ void dinv_k()
{
    int i = blockIdx.x * blockDim.x + threadIdx.x;
    if (i < NN) g_dinv[i] = rsqrtf(g_deg[i]);
}
__global__ void norm_k(const int* __restrict__ src, const int* __restrict__ dst,
                       const float* __restrict__ w)
{
    int e = blockIdx.x * blockDim.x + threadIdx.x;
    if (e < EE) g_norm[e] = g_dinv[src[e]] * w[e] * g_dinv[dst[e]];
}

// ---------------- weight prep: W[k][n] fp32 -> [n][k] bf16 hi/lo -----------
template<int L, int KDIM>
__global__ void wprep_k(const float* __restrict__ W)
{
    int n = blockIdx.x;
    for (int k = threadIdx.x; k < KDIM; k += 256) {
        float v = W[(size_t)k * HH + n];
        uint16_t h, l;
        split_bf16(v, h, l);
        g_whi[L][(size_t)n * WSTR + k] = h;
        g_wlo[L][(size_t)n * WSTR + k] = l;
    }
}

// ---------------- activation split: p -> bn+relu -> bf16 hi/lo -------------
template<int SRCL>
__global__ void asplit_k()
{
    const float* src = (SRCL == 0) ? g_p1 : g_p2;
    size_t idx = ((size_t)blockIdx.x * blockDim.x + threadIdx.x) * 4;
    int j = (int)(idx & (HH - 1));
    float4 v = *(const float4*)(src + idx);
    float4 s = *(const float4*)(g_scale + SRCL * HH + j);
    float4 h = *(const float4*)(g_shift + SRCL * HH + j);
    float a0 = fmaxf(fmaf(v.x, s.x, h.x), 0.f);
    float a1 = fmaxf(fmaf(v.y, s.y, h.y), 0.f);
    float a2 = fmaxf(fmaf(v.z, s.z, h.z), 0.f);
    float a3 = fmaxf(fmaf(v.w, s.w, h.w), 0.f);
    ushort4 uh, ul;
    split_bf16(a0, uh.x, ul.x);
    split_bf16(a1, uh.y, ul.y);
    split_bf16(a2, uh.z, ul.z);
    split_bf16(a3, uh.w, ul.w);
    *(ushort4*)(g_ahi + idx) = uh;
    *(ushort4*)(g_alo + idx) = ul;
}

// ---------------- residual combine -> bf16 hi/lo ---------------------------
__global__ void combine_split_k()
{
    size_t idx = ((size_t)blockIdx.x * blockDim.x + threadIdx.x) * 4;
    int j = (int)(idx & (HH - 1));
    float4 a = *(const float4*)(g_p1 + idx);
    float4 b = *(const float4*)(g_p2 + idx);
    float4 c = *(const float4*)(g_p3 + idx);
    float4 s, h;
    float r0, r1, r2, r3;
    s = *(const float4*)(g_scale + j);       h = *(const float4*)(g_shift + j);
    r0 = fmaxf(fmaf(a.x, s.x, h.x), 0.f);
    r1 = fmaxf(fmaf(a.y, s.y, h.y), 0.f);
    r2 = fmaxf(fmaf(a.z, s.z, h.z), 0.f);
    r3 = fmaxf(fmaf(a.w, s.w, h.w), 0.f);
    s = *(const float4*)(g_scale + HH + j);  h = *(const float4*)(g_shift + HH + j);
    r0 += fmaxf(fmaf(b.x, s.x, h.x), 0.f);
    r1 += fmaxf(fmaf(b.y, s.y, h.y), 0.f);
    r2 += fmaxf(fmaf(b.z, s.z, h.z), 0.f);
    r3 += fmaxf(fmaf(b.w, s.w, h.w), 0.f);
    s = *(const float4*)(g_scale + 2*HH + j); h = *(const float4*)(g_shift + 2*HH + j);
    r0 += fmaxf(fmaf(c.x, s.x, h.x), 0.f);
    r1 += fmaxf(fmaf(c.y, s.y, h.y), 0.f);
    r2 += fmaxf(fmaf(c.z, s.z, h.z), 0.f);
    r3 += fmaxf(fmaf(c.w, s.w, h.w), 0.f);
    ushort4 uh, ul;
    split_bf16(r0, uh.x, ul.x);
    split_bf16(r1, uh.y, ul.y);
    split_bf16(r2, uh.z, ul.z);
    split_bf16(r3, uh.w, ul.w);
    *(ushort4*)(g_ahi + idx) = uh;
    *(ushort4*)(g_alo + idx) = ul;
}

// ---------------- split-bf16 HMMA GEMM (pre-split inputs) -------------------
// C[128 x 128/CTA] = A[.,KDIM] @ W  via hi*hi + hi*lo + lo*hi, fp32 accum.
// MODE 0: C -> g_t ; MODE 1: out = tanh(acc + bias). WL = weight table index.
template<int MODE, int KDIM, int WL>
__global__ void __launch_bounds__(256) gemm_hmma(
    float* __restrict__ outC, const float* __restrict__ bias)
{
    __shared__ uint16_t sAhi[128 * SAPAD];
    __shared__ uint16_t sAlo[128 * SAPAD];
    __shared__ uint16_t sBhi[128 * SAPAD];
    __shared__ uint16_t sBlo[128 * SAPAD];

    const int tid  = threadIdx.x;
    const int wid  = tid >> 5;
    const int lane = tid & 31;
    const int g    = lane >> 2;
    const int tig  = lane & 3;
    const int wm   = wid & 3;          // warp m-tile (32 rows)
    const int wn   = wid >> 2;         // warp n-tile (64 cols)

    const int n0 = blockIdx.x * 128;
    const size_t rowBase = (size_t)blockIdx.y * 128;
    const uint16_t* Whi = g_whi[WL];
    const uint16_t* Wlo = g_wlo[WL];

    // staging addresses (each thread handles 2 uint4 per tile array)
    const int sIdx0 = tid, sIdx1 = tid + 256;     // 0..511
    const int aR0 = sIdx0 >> 2, aQ0 = sIdx0 & 3;
    const int aR1 = sIdx1 >> 2, aQ1 = sIdx1 & 3;

    float acc[2][8][4];
    #pragma unroll
    for (int fm = 0; fm < 2; ++fm)
        #pragma unroll
        for (int fn = 0; fn < 8; ++fn)
            #pragma unroll
            for (int q = 0; q < 4; ++q) acc[fm][fn][q] = 0.f;

    constexpr int CHUNKS = KDIM / 32;
    uint4 rAhi[2], rAlo[2], rBhi[2], rBlo[2];

    // prologue: load chunk 0
    {
        const size_t a0 = (rowBase + aR0) * KDIM + aQ0 * 8;
        const size_t a1 = (rowBase + aR1) * KDIM + aQ1 * 8;
        const size_t b0 = (size_t)(n0 + aR0) * WSTR + aQ0 * 8;
        const size_t b1 = (size_t)(n0 + aR1) * WSTR + aQ1 * 8;
        rAhi[0] = *(const uint4*)(g_ahi + a0); rAhi[1] = *(const uint4*)(g_ahi + a1);
        rAlo[0] = *(const uint4*)(g_alo + a0); rAlo[1] = *(const uint4*)(g_alo + a1);
        rBhi[0] = *(const uint4*)(Whi + b0);   rBhi[1] = *(const uint4*)(Whi + b1);
        rBlo[0] = *(const uint4*)(Wlo + b0);   rBlo[1] = *(const uint4*)(Wlo + b1);
    }

    for (int c = 0; c < CHUNKS; ++c) {
        // store staged chunk to smem
        *(uint4*)&sAhi[aR0 * SAPAD + aQ0 * 8] = rAhi[0];
        *(uint4*)&sAhi[aR1 * SAPAD + aQ1 * 8] = rAhi[1];
        *(uint4*)&sAlo[aR0 * SAPAD + aQ0 * 8] = rAlo[0];
        *(uint4*)&sAlo[aR1 * SAPAD + aQ1 * 8] = rAlo[1];
        *(uint4*)&sBhi[aR0 * SAPAD + aQ0 * 8] = rBhi[0];
        *(uint4*)&sBhi[aR1 * SAPAD + aQ1 * 8] = rBhi[1];
        *(uint4*)&sBlo[aR0 * SAPAD + aQ0 * 8] = rBlo[0];
        *(uint4*)&sBlo[aR1 * SAPAD + aQ1 * 8] = rBlo[1];
        __syncthreads();

        // issue loads for next chunk early (hide gmem latency under MMA)
        if (c + 1 < CHUNKS) {
            const int k0 = (c + 1) * 32;
            const size_t a0 = (rowBase + aR0) * KDIM + k0 + aQ0 * 8;
            const size_t a1 = (rowBase + aR1) * KDIM + k0 + aQ1 * 8;
            const size_t b0 = (size_t)(n0 + aR0) * WSTR + k0 + aQ0 * 8;
            const size_t b1 = (size_t)(n0 + aR1) * WSTR + k0 + aQ1 * 8;
            rAhi[0] = *(const uint4*)(g_ahi + a0); rAhi[1] = *(const uint4*)(g_ahi + a1);
            rAlo[0] = *(const uint4*)(g_alo + a0); rAlo[1] = *(const uint4*)(g_alo + a1);
            rBhi[0] = *(const uint4*)(Whi + b0);   rBhi[1] = *(const uint4*)(Whi + b1);
            rBlo[0] = *(const uint4*)(Wlo + b0);   rBlo[1] = *(const uint4*)(Wlo + b1);
        }

        // MMA over this chunk
        #pragma unroll
        for (int ks = 0; ks < 2; ++ks) {
            const int kc = ks * 16 + 2 * tig;
            uint32_t af[2][2][4];
            #pragma unroll
            for (int fm = 0; fm < 2; ++fm) {
                int r0 = (wm * 32 + fm * 16 + g) * SAPAD;
                int r1 = r0 + 8 * SAPAD;
                af[0][fm][0] = *(uint32_t*)&sAhi[r0 + kc];
                af[0][fm][1] = *(uint32_t*)&sAhi[r1 + kc];
                af[0][fm][2] = *(uint32_t*)&sAhi[r0 + kc + 8];
                af[0][fm][3] = *(uint32_t*)&sAhi[r1 + kc + 8];
                af[1][fm][0] = *(uint32_t*)&sAlo[r0 + kc];
                af[1][fm][1] = *(uint32_t*)&sAlo[r1 + kc];
                af[1][fm][2] = *(uint32_t*)&sAlo[r0 + kc + 8];
                af[1][fm][3] = *(uint32_t*)&sAlo[r1 + kc + 8];
            }
            #pragma unroll
            for (int fn = 0; fn < 8; ++fn) {
                int bn = (wn * 64 + fn * 8 + g) * SAPAD;
                uint32_t bh0 = *(uint32_t*)&sBhi[bn + kc];
                uint32_t bh1 = *(uint32_t*)&sBhi[bn + kc + 8];
                uint32_t bl0 = *(uint32_t*)&sBlo[bn + kc];
                uint32_t bl1 = *(uint32_t*)&sBlo[bn + kc + 8];
                #pragma unroll
                for (int fm = 0; fm < 2; ++fm) {
                    mma_bf16(acc[fm][fn], af[0][fm], bh0, bh1);   // hi*hi
                    mma_bf16(acc[fm][fn], af[0][fm], bl0, bl1);   // hi*lo
                    mma_bf16(acc[fm][fn], af[1][fm], bh0, bh1);   // lo*hi
                }
            }
        }
        __syncthreads();
    }

    // ---- epilogue ----------------------------------------------------------
    float* Cout = (MODE == 0) ? g_t : outC;
    #pragma unroll
    for (int fm = 0; fm < 2; ++fm) {
        size_t r0 = rowBase + wm * 32 + fm * 16 + g;
        size_t r1 = r0 + 8;
        #pragma unroll
        for (int fn = 0; fn < 8; ++fn) {
            int col = n0 + wn * 64 + fn * 8 + 2 * tig;
            float2 v0, v1;
            if (MODE == 0) {
                v0.x = acc[fm][fn][0]; v0.y = acc[fm][fn][1];
                v1.x = acc[fm][fn][2]; v1.y = acc[fm][fn][3];
            } else {
                float bx = bias[col], by = bias[col + 1];
                v0.x = tanhf(acc[fm][fn][0] + bx);
                v0.y = tanhf(acc[fm][fn][1] + by);
                v1.x = tanhf(acc[fm][fn][2] + bx);
                v1.y = tanhf(acc[fm][fn][3] + by);
            }
            *(float2*)(Cout + r0 * HH + col) = v0;
            *(float2*)(Cout + r1 * HH + col) = v1;
        }
    }
}

// ---------------- per-graph aggregation -------------------------------------
template<int L>
__global__ void __launch_bounds__(64) agg_k(
    const int* __restrict__ src, const int* __restrict__ dst,
    const float* __restrict__ bias)
{
    __shared__ float sIn [TT * CH];
    __shared__ float sAcc[TT * CH];
    __shared__ float sNorm[EPG];
    __shared__ float sSelf[TT];
    __shared__ int   sSrc[EPG];
    __shared__ int   sDst[EPG];

    float* pout = (L == 0) ? g_p1 : (L == 1) ? g_p2 : g_p3;

    const int b   = blockIdx.x;
    const int c0  = blockIdx.y * CH;
    const int tid = threadIdx.x;

    const float* base = g_t + (size_t)b * TT * HH + c0;
    for (int i = tid; i < TT * CH; i += 64) {
        int node = i / CH, c = i & (CH - 1);
        sIn[i]  = base[(size_t)node * HH + c];
        sAcc[i] = 0.f;
    }
    for (int e = tid; e < EPG; e += 64) {
        sSrc[e]  = src[b * EPG + e] - b * TT;
        sDst[e]  = dst[b * EPG + e] - b * TT;
        sNorm[e] = g_norm[b * EPG + e];
    }
    for (int i = tid; i < TT; i += 64) {
        float d = g_dinv[b * TT + i];
        sSelf[i] = d * d;
    }
    __syncthreads();

    const int c = tid;
    #pragma unroll 4
    for (int e = 0; e < EPG; ++e) {
        sAcc[sDst[e] * CH + c] += sIn[sSrc[e] * CH + c] * sNorm[e];
    }

    const float bc = bias[c0 + c];
    float sum = 0.f, sq = 0.f;
    for (int node = 0; node < TT; ++node) {
        float v = sAcc[node * CH + c] + sIn[node * CH + c] * sSelf[node] + bc;
        pout[(size_t)(b * TT + node) * HH + c0 + c] = v;
        sum += v;
        sq  += v * v;
    }
    atomicAdd(&g_stats[c0 + c], sum);
    atomicAdd(&g_stats[HH + c0 + c], sq);
}

// ---------------- BN finalize ------------------------------------------------
template<int L>
__global__ void bnfinal_k(const float* __restrict__ g, const float* __restrict__ be)
{
    int c = threadIdx.x;
    float s = g_stats[c], sq = g_stats[HH + c];
    const float inv = 1.0f / (float)NN;
    float mean = s * inv;
    float var  = sq * inv - mean * mean;
    float rstd = rsqrtf(var + 1e-5f);
    float scl  = g[c] * rstd;
    g_scale[L * HH + c] = scl;
    g_shift[L * HH + c] = fmaf(-mean, scl, be[c]);
    g_stats[c] = 0.f;
    g_stats[HH + c] = 0.f;
}

// ---------------- host driver ------------------------------------------------
extern "C" void kernel_launch(void* const* d_in, const int* in_sizes, int n_in,
                              void* d_out, int out_size)
{
    (void)in_sizes; (void)n_in; (void)out_size;

    const float* x      = (const float*)d_in[0];
    const int*   eidx   = (const int*)  d_in[1];
    const int*   esrc   = eidx;
    const int*   edst   = eidx + EE;
    const float* ew     = (const float*)d_in[2];
    const int*   pos    = (const int*)  d_in[3];
    const float* posemb = (const float*)d_in[4];
    const float* W1 = (const float*)d_in[5];
    const float* b1 = (const float*)d_in[6];
    const float* g1 = (const float*)d_in[7];
    const float* be1= (const float*)d_in[8];
    const float* W2 = (const float*)d_in[9];
    const float* b2 = (const float*)d_in[10];
    const float* g2 = (const float*)d_in[11];
    const float* be2= (const float*)d_in[12];
    const float* W3 = (const float*)d_in[13];
    const float* b3 = (const float*)d_in[14];
    const float* g3 = (const float*)d_in[15];
    const float* be3= (const float*)d_in[16];
    const float* Wl = (const float*)d_in[17];
    const float* bl = (const float*)d_in[18];
    float* out = (float*)d_out;

    dim3 aGrid(NB, HH / CH);          // (2048, 8)
    dim3 gGrid(HH / 128, NN / 128);   // (4, 800)
    const int SPLIT_BLOCKS = (NN * HH / 4) / 256;   // 51200

    // 0) concat(split) + normalization + weight prep
    concat_split_k<<<NN, KIN>>>(x, pos, posemb);
    deg_init_k<<<(NN + 255) / 256, 256>>>();
    deg_acc_k<<<(EE + 255) / 256, 256>>>(edst, ew);
    dinv_k<<<(NN + 255) / 256, 256>>>();
    norm_k<<<(EE + 255) / 256, 256>>>(esrc, edst, ew);
    wprep_k<0, KIN><<<HH, 256>>>(W1);
    wprep_k<1, HH><<<HH, 256>>>(W2);
    wprep_k<2, HH><<<HH, 256>>>(W3);
    wprep_k<3, HH><<<HH, 256>>>(Wl);

    // layer 1
    gemm_hmma<0, KIN, 0><<<gGrid, 256>>>(nullptr, nullptr);
    agg_k<0><<<aGrid, 64>>>(esrc, edst, b1);
    bnfinal_k<0><<<1, HH>>>(g1, be1);
    asplit_k<0><<<SPLIT_BLOCKS, 256>>>();

    // layer 2
    gemm_hmma<0, HH, 1><<<gGrid, 256>>>(nullptr, nullptr);
    agg_k<1><<<aGrid, 64>>>(esrc, edst, b2);
    bnfinal_k<1><<<1, HH>>>(g2, be2);
    asplit_k<1><<<SPLIT_BLOCKS, 256>>>();

    // layer 3
    gemm_hmma<0, HH, 2><<<gGrid, 256>>>(nullptr, nullptr);
    agg_k<2><<<aGrid, 64>>>(esrc, edst, b3);
    bnfinal_k<2><<<1, HH>>>(g3, be3);

    // residual combine (split) + final head
    combine_split_k<<<SPLIT_BLOCKS, 256>>>();
    gemm_hmma<1, HH, 3><<<gGrid, 256>>>(out, bl);
}